// round 10
// baseline (speedup 1.0000x reference)
#include <cuda_runtime.h>
#include <cuda_bf16.h>
#include <math_constants.h>
#include <cooperative_groups.h>
namespace cg = cooperative_groups;

#define B 16
#define N 8400
#define M 32
#define C 80
#define TOPK 13

// Output layout (f32 elements), tuple flattened & concatenated:
#define L0 0                      // target_labels  (B,N)
#define L1 (B*N)                  // target_bboxes  (B,N,4)
#define L2 (L1 + B*N*4)           // target_scores  (B,N,C)
#define L3 (L2 + B*N*C)           // fg_mask        (B,N)
#define L4 (L3 + B*N)             // target_gt_idx  (B,N)

#define NT 512
#define NW (NT/32)                // 16 warps
#define ZBLK 128                  // zero-duty blocks
#define GRID_ROWS 640             // bid%5==4 -> zero duty (128), else row (512)
#define QCAP 1408                 // >= max in-box anchors per gt (1344 proven)

// Scratch (device globals; zero-initialized at load; self-cleaning across calls)
__device__ float    g_over [B*M*N];    // overlaps, valid rows only
__device__ float    g_anorm[B*N];      // stashed align metric for fg anchors
__device__ unsigned g_maskpos[B*N];    // OR-accumulated bits; zeroed by k_scatter
__device__ float    g_posalign[B*M];   // zeroed by zero-duty blocks
__device__ float    g_posover [B*M];
__device__ unsigned g_valid[B];        // zeroed by k_scatter

typedef unsigned long long u64;

// ---------------------------------------------------------------------------
// k_rowsZ: grid 640, 512 threads.
//   bid%5==4 : zero-duty — fill target_scores region + pos arrays with 0.
//   else     : compute gt row bm. Phase A: CIoU row; positive-align keys
//              pushed to a smem queue with a COALESCED-GROUP aggregated
//              atomic (1 atomic per positive cluster, divergence-legal);
//              zero-align anchors recorded in per-thread zmask.
//              Phase B: single-pass rank selection — each thread counts how
//              many queue keys beat each of its entries (uniform inner index
//              -> broadcast LDS); rank < 13 => pick. Exact fallback for <13
//              positives via zmask block-min rounds. Scatter mask bits.
// Key packing: (float_bits(align) << 32) | (8400 - n): max => value desc,
// ties -> lower n (jax.lax.top_k order). Positive keys unique, >= 2^32.
// Queue order nondeterministic; rank selection is order-invariant.
// ---------------------------------------------------------------------------
__global__ __launch_bounds__(NT) void k_rowsZ(
    const float* __restrict__ ps,      // pd_scores (B,N,C)
    const float* __restrict__ pb,      // pd_bboxes (B,N,4)
    const float* __restrict__ anc,     // anc_points (N,2)
    const int*   __restrict__ labels,  // gt_labels (B,M,1)
    const float* __restrict__ gtb,     // gt_bboxes (B,M,4)
    const unsigned char* __restrict__ mask_raw,  // mask_gt, dtype unknown
    float*       __restrict__ out)
{
    const int bid = blockIdx.x;
    const int t   = threadIdx.x;
    const int r   = bid % 5, q5 = bid / 5;

    if (r == 4) {   // ---- zero duty ----
        const float4 z4 = make_float4(0.f, 0.f, 0.f, 0.f);
        for (int i = q5*NT + t; i < B*N*C/4; i += ZBLK*NT)
            ((float4*)(out + L2))[i] = z4;
        if (q5 == 0 && t < B*M) { g_posalign[t] = 0.f; g_posover[t] = 0.f; }
        return;
    }

    const int bm = q5*4 + r;           // 0..511
    const int b  = bm >> 5;
    const int m  = bm & 31;

    __shared__ u64 q[QCAP];
    __shared__ u64 warpred[NW];
    __shared__ u64 s_best;
    __shared__ int picks[TOPK];
    __shared__ int qc_sh;

    if (t == 0) qc_sh = 0;
    if (t < TOPK) picks[t] = -1;

    // Detect mask_gt dtype (uint8 bool vs int32): int32 {0,1} data has zero
    // bytes at offsets p%4!=0. Block-uniform result. (Doubles as the barrier
    // after the qc_sh/picks init.)
    int bad = 0;
    if (t < 512 && (t & 3) != 0 && mask_raw[t] != 0) bad = 1;
    const int is_u8 = __syncthreads_or(bad);

    const int mg = is_u8 ? (int)mask_raw[bm] : ((const int*)mask_raw)[bm];
    if (!mg) return;
    if (t == 0) atomicOr(&g_valid[b], 1u << m);

    float* __restrict__ orow = g_over + (size_t)bm * N;

    const float4 gt = ((const float4*)gtb)[bm];
    const int cls = labels[bm];
    const float gx1 = gt.x, gy1 = gt.y, gx2 = gt.z, gy2 = gt.w;
    const float w1  = gx2 - gx1;
    const float h1  = gy2 - gy1 + 1e-7f;
    const float at1 = atanf(w1 / h1);
    const float inv_pi2_4 = 4.0f / (CUDART_PI_F * CUDART_PI_F);

    const int wid = t >> 5, lane = t & 31;

    // ---- phase A: CIoU row; aggregated push; zmask for zero-align anchors --
    u64 zmask = 0ull;
    int it = 0;
    for (int n = t; n < N; n += NT, it++) {
        const float2 a2 = ((const float2*)anc)[n];
        const float ax = a2.x, ay = a2.y;
        const float dmin = fminf(fminf(ax - gx1, ay - gy1),
                                 fminf(gx2 - ax, gy2 - ay));
        float o = 0.f, al = 0.f;
        if (dmin > 1e-9f) {
            const float4 p = ((const float4*)pb)[b*N + n];
            const float px1 = p.x, py1 = p.y, px2 = p.z, py2 = p.w;
            const float iw = fmaxf(fminf(gx2, px2) - fmaxf(gx1, px1), 0.f);
            const float ih = fmaxf(fminf(gy2, py2) - fmaxf(gy1, py1), 0.f);
            const float inter = iw * ih;
            const float w2 = px2 - px1;
            const float h2 = py2 - py1 + 1e-7f;
            const float uni = w1*h1 + w2*h2 - inter + 1e-7f;
            const float iou = inter / uni;
            const float cw = fmaxf(gx2, px2) - fminf(gx1, px1);
            const float ch = fmaxf(gy2, py2) - fminf(gy1, py1);
            const float c2 = cw*cw + ch*ch + 1e-7f;
            const float dx = px1 + px2 - gx1 - gx2;
            const float dy = py1 + py2 - gy1 - gy2;
            const float rho2 = (dx*dx + dy*dy) * 0.25f;
            const float dat = atanf(w2 / h2) - at1;
            const float v = inv_pi2_4 * dat * dat;
            const float a = v / (v - iou + 1.0f + 1e-7f);
            const float ciou = iou - (rho2 / c2 + v * a);
            o = fmaxf(ciou, 0.f);
            const float s = ps[(b*N + n)*C + cls];
            const float o2 = o * o;
            al = s * (o2 * o2 * o2);   // s^alpha * o^beta
        }
        orow[n] = o;

        if (al > 0.f) {
            // Divergence-legal warp aggregation: one atomic per cluster.
            cg::coalesced_group g = cg::coalesced_threads();
            int base = 0;
            if (g.thread_rank() == 0) base = atomicAdd(&qc_sh, (int)g.size());
            base = g.shfl(base, 0);
            const int slot = base + (int)g.thread_rank();
            if (slot < QCAP)
                q[slot] = ((u64)__float_as_uint(al) << 32) | (unsigned)(N - n);
        } else {
            zmask |= (1ull << it);
        }
    }
    __syncthreads();
    const int qc = (qc_sh < QCAP) ? qc_sh : QCAP;

    // ---- phase B: single-pass rank selection over the queue ----
    // For each owned entry, count keys greater than it. Inner index j is
    // block-uniform -> broadcast LDS. rank < TOPK => that entry is pick[rank].
    for (int i = t; i < qc; i += NT) {
        const u64 my = q[i];
        int rank = 0;
        for (int j = 0; j < qc; j++)
            rank += (q[j] > my);
        if (rank < TOPK)
            picks[rank] = N - (int)(unsigned)(my & 0xffffffffull);
    }
    __syncthreads();

    // ---- exact fallback: fewer than 13 positives -> lowest-n zero anchors --
    const int npos = (qc < TOPK) ? qc : TOPK;
    if (npos < TOPK) {
        for (int k = npos; k < TOPK; k++) {
            const u64 myn = zmask ? (u64)(t + NT * (__ffsll((long long)zmask) - 1))
                                  : (u64)0x7fffffff;
            u64 best = myn;
            #pragma unroll
            for (int off = 16; off > 0; off >>= 1) {
                const u64 hh = __shfl_xor_sync(0xffffffffu, best, off);
                best = (hh < best) ? hh : best;
            }
            if (lane == 0) warpred[wid] = best;
            __syncthreads();
            if (wid == 0) {
                u64 bb = (lane < NW) ? warpred[lane] : (u64)0x7fffffff;
                #pragma unroll
                for (int off = 8; off > 0; off >>= 1) {
                    const u64 hh = __shfl_xor_sync(0xffffffffu, bb, off);
                    bb = (hh < bb) ? hh : bb;
                }
                if (lane == 0) {
                    s_best = bb;
                    picks[k] = (bb < (u64)0x7fffffff) ? (int)bb : -1;
                }
            }
            __syncthreads();
            if (myn == s_best) zmask &= (zmask - 1ull);   // consume my bit
        }
    }

    // ---- scatter: mask_pos = mask_topk & mask_in_gts ----
    if (t < TOPK) {
        const int n = picks[t];
        if (n >= 0) {
            const float2 a2 = ((const float2*)anc)[n];
            const float dmin = fminf(fminf(a2.x - gx1, a2.y - gy1),
                                     fminf(gx2 - a2.x, gy2 - a2.y));
            if (dmin > 1e-9f)
                atomicOr(&g_maskpos[b*N + n], 1u << m);
        }
    }
}

// ---------------------------------------------------------------------------
// k_assign: per (b,n). Resolves multi-assignment (argmax scan only if some
// lane in the warp needs it), writes labels/bboxes/fg/tgi outputs, stashes
// align metric, accumulates per-gt pos maxima.
// ---------------------------------------------------------------------------
__global__ __launch_bounds__(256) void k_assign(
    const float* __restrict__ ps,
    const int*   __restrict__ labels,
    const float* __restrict__ gtb,
    float*       __restrict__ out)
{
    const int idx = blockIdx.x * 256 + threadIdx.x;   // grid exactly B*N/256
    const int b = idx / N;
    const int n = idx - b * N;

    const unsigned u  = g_maskpos[idx];
    const unsigned vm = g_valid[b];
    const bool multi  = __popc(u) > 1;

    int bestm = 0;
    if (__ballot_sync(0xffffffffu, multi)) {
        float bv = -1.f;
        const int base = b * M * N + n;
        #pragma unroll
        for (int m = 0; m < M; m++) {
            const float v = ((vm >> m) & 1u) ? g_over[base + m*N] : 0.f;
            if (v > bv) { bv = v; bestm = m; }
        }
    }

    const unsigned f = multi ? (1u << bestm) : u;
    g_maskpos[idx] = f;

    const int tgi = f ? (__ffs((int)f) - 1) : 0;
    const int bmE = b * M + tgi;
    const int lab = labels[bmE];

    out[L0 + idx] = (float)lab;
    ((float4*)(out + L1))[idx] = ((const float4*)gtb)[bmE];
    out[L3 + idx] = f ? 1.f : 0.f;
    out[L4 + idx] = (float)tgi;

    if (f) {
        const float o  = g_over[bmE*N + n];
        const float s  = ps[(size_t)idx * C + lab];
        const float o2 = o * o;
        const float a  = s * (o2 * o2 * o2);
        g_anorm[idx] = a;
        atomicMax((int*)&g_posalign[bmE], __float_as_int(a));
        atomicMax((int*)&g_posover [bmE], __float_as_int(o));
    }
}

// ---------------------------------------------------------------------------
// k_scatter: sparse write of the single nonzero target_scores element per
// foreground anchor; self-cleans g_maskpos / g_valid for the next call.
// ---------------------------------------------------------------------------
__global__ __launch_bounds__(256) void k_scatter(
    const int* __restrict__ labels,
    float*     __restrict__ out)
{
    const int idx = blockIdx.x * 256 + threadIdx.x;
    const unsigned f = g_maskpos[idx];
    g_maskpos[idx] = 0u;                 // self-clean for next call
    if (idx < B) g_valid[idx] = 0u;
    if (!f) return;
    const int b = idx / N;
    const int m = __ffs((int)f) - 1;
    const int bmE = b * M + m;
    const float a = g_anorm[idx];
    const float norm = a * g_posover[bmE] / (g_posalign[bmE] + 1e-9f);
    out[L2 + (size_t)idx * C + labels[bmE]] = norm;
}

extern "C" void kernel_launch(void* const* d_in, const int* in_sizes, int n_in,
                              void* d_out, int out_size) {
    const float* ps     = (const float*)d_in[0];
    const float* pb     = (const float*)d_in[1];
    const float* anc    = (const float*)d_in[2];
    const int*   labels = (const int*)  d_in[3];
    const float* gtb    = (const float*)d_in[4];
    const unsigned char* maskg = (const unsigned char*)d_in[5];
    float* out = (float*)d_out;

    k_rowsZ<<<GRID_ROWS, NT>>>(ps, pb, anc, labels, gtb, maskg, out);
    k_assign<<<(B*N)/256, 256>>>(ps, labels, gtb, out);
    k_scatter<<<(B*N)/256, 256>>>(labels, out);
}